// round 1
// baseline (speedup 1.0000x reference)
#include <cuda_runtime.h>
#include <math.h>

// ---------------- problem constants ----------------
#define SQ   2048
#define NB   4
#define EE   1024
#define FF   4096
#define NEXP 8
#define CAPN 2048
#define NH   16
#define HD   64
#define TOK  (SQ*NB)          // 8192 tokens

// ---------------- GEMM tile config ----------------
#define BM 64
#define BN 64
#define BK 16

// ---------------- scratch (device globals; no allocation allowed) ----------------
__device__ float g_qn[TOK*EE];
__device__ float g_kn[TOK*EE];
__device__ float g_vn[TOK*EE];
__device__ float g_qp[TOK*EE];
__device__ float g_kp[TOK*EE];
__device__ float g_vp[TOK*EE];
__device__ float g_ctx[TOK*EE];
__device__ float g_x[TOK*EE];          // residual after attention
__device__ float g_xn[TOK*EE];         // LN2 output
__device__ float g_h[(size_t)NEXP*CAPN*FF];   // expert hidden activations (256MB)
__device__ int   g_eid[TOK];
__device__ int   g_list[NEXP*CAPN];
__device__ int   g_cnt[NEXP];

// ---------------- block reduction helper (deterministic) ----------------
__device__ __forceinline__ float blk_sum256(float v) {
    __shared__ float red[8];
    #pragma unroll
    for (int o = 16; o > 0; o >>= 1) v += __shfl_xor_sync(0xffffffffu, v, o);
    if ((threadIdx.x & 31) == 0) red[threadIdx.x >> 5] = v;
    __syncthreads();
    float s = 0.f;
    #pragma unroll
    for (int i = 0; i < 8; i++) s += red[i];
    __syncthreads();
    return s;
}

// ---------------- LN (+ optional RoPE) ----------------
__device__ __forceinline__ void ln_rope_body(const float* __restrict__ x,
                                             float* __restrict__ o,
                                             const float* __restrict__ sc,
                                             const float* __restrict__ bi,
                                             int srow, int do_rope) {
    float s = 0.f;
    for (int i = threadIdx.x; i < EE; i += 256) s += x[i];
    float mean = blk_sum256(s) * (1.0f / EE);
    float vs = 0.f;
    for (int i = threadIdx.x; i < EE; i += 256) { float d = x[i] - mean; vs += d * d; }
    float var = blk_sum256(vs) * (1.0f / EE);
    float rstd = rsqrtf(var + 1e-5f);
    if (do_rope) {
        for (int i = threadIdx.x; i < EE / 2; i += 256) {
            float x1 = (x[i]        - mean) * rstd * sc[i]        + bi[i];
            float x2 = (x[i + 512]  - mean) * rstd * sc[i + 512]  + bi[i + 512];
            float inv = (float)(1.0 / pow(10000.0, (double)i * (1.0 / 512.0)));
            float fr = (float)srow * inv;
            float sn, cs;
            sincosf(fr, &sn, &cs);
            o[i]       = x1 * cs - x2 * sn;
            o[i + 512] = x1 * sn + x2 * cs;
        }
    } else {
        for (int i = threadIdx.x; i < EE; i += 256)
            o[i] = (x[i] - mean) * rstd * sc[i] + bi[i];
    }
}

__global__ void ln1_rope_kernel(const float* __restrict__ q, const float* __restrict__ k,
                                const float* __restrict__ v,
                                const float* __restrict__ sc, const float* __restrict__ bi) {
    int z = blockIdx.y;
    const float* in = (z == 0) ? q : (z == 1) ? k : v;
    float* out = (z == 0) ? g_qn : (z == 1) ? g_kn : g_vn;
    int t = blockIdx.x;
    ln_rope_body(in + (size_t)t * EE, out + (size_t)t * EE, sc, bi, t / NB, 1);
}

__global__ void ln2_kernel(const float* __restrict__ sc, const float* __restrict__ bi) {
    int t = blockIdx.x;
    ln_rope_body(g_x + (size_t)t * EE, g_xn + (size_t)t * EE, sc, bi, 0, 0);
}

// ---------------- generic 64x64x16 fp32 GEMM core ----------------
// BT=true : B stored [N,K] row-major (C = A * B^T)
// BT=false: B stored [K,N] row-major (C = A * B)
// optional row gather for A, rows clamped to valid-1 (store guarded by caller)
template<bool BT>
__device__ __forceinline__ void gemm_core(const float* __restrict__ A, int lda,
                                          const float* __restrict__ Bm, int ldb,
                                          int K, int row0, int col0,
                                          const int* __restrict__ gather, int valid,
                                          float acc[4][4]) {
    __shared__ float As[BK][BM + 4];
    __shared__ float Bs[BK][BN + 4];
    const int tid = threadIdx.x;
    const int tx = tid & 15, ty = tid >> 4;

    int arow[4];
    #pragma unroll
    for (int i = 0; i < 4; i++) {
        int id = tid + i * 256;
        int r = id >> 4;
        int gr = row0 + r; if (gr > valid - 1) gr = valid - 1;
        arow[i] = gather ? gather[gr] : gr;
    }

    for (int k0 = 0; k0 < K; k0 += BK) {
        #pragma unroll
        for (int i = 0; i < 4; i++) {
            int id = tid + i * 256;
            int r = id >> 4, c = id & 15;
            As[c][r] = A[(size_t)arow[i] * lda + k0 + c];
        }
        if (BT) {
            #pragma unroll
            for (int i = 0; i < 4; i++) {
                int id = tid + i * 256;
                int r = id >> 4, c = id & 15;
                Bs[c][r] = Bm[(size_t)(col0 + r) * ldb + k0 + c];
            }
        } else {
            #pragma unroll
            for (int i = 0; i < 4; i++) {
                int id = tid + i * 256;
                int r = id >> 6, c = id & 63;
                Bs[r][c] = Bm[(size_t)(k0 + r) * ldb + col0 + c];
            }
        }
        __syncthreads();
        #pragma unroll
        for (int kk = 0; kk < BK; kk++) {
            float4 a4 = *reinterpret_cast<const float4*>(&As[kk][ty * 4]);
            float4 b4 = *reinterpret_cast<const float4*>(&Bs[kk][tx * 4]);
            float av[4] = {a4.x, a4.y, a4.z, a4.w};
            float bv[4] = {b4.x, b4.y, b4.z, b4.w};
            #pragma unroll
            for (int i = 0; i < 4; i++)
                #pragma unroll
                for (int j = 0; j < 4; j++)
                    acc[i][j] = fmaf(av[i], bv[j], acc[i][j]);
        }
        __syncthreads();
    }
}

// ---------------- QKV projection: C = LN(x) @ W^T + b ----------------
__global__ void qkv_proj_kernel(const float* __restrict__ W, const float* __restrict__ bias) {
    int z = blockIdx.z;
    const float* A = (z == 0) ? g_qn : (z == 1) ? g_kn : g_vn;
    float* C = (z == 0) ? g_qp : (z == 1) ? g_kp : g_vp;
    int row0 = blockIdx.y * BM, col0 = blockIdx.x * BN;
    float acc[4][4] = {};
    gemm_core<true>(A, EE, W + (size_t)z * EE * EE, EE, EE, row0, col0, nullptr, TOK, acc);
    int tx = threadIdx.x & 15, ty = threadIdx.x >> 4;
    #pragma unroll
    for (int i = 0; i < 4; i++) {
        int r = row0 + ty * 4 + i;
        #pragma unroll
        for (int j = 0; j < 4; j++) {
            int c = col0 + tx * 4 + j;
            C[(size_t)r * EE + c] = acc[i][j] + bias[z * EE + c];
        }
    }
}

// ---------------- out projection + bias + residual(query) ----------------
__global__ void out_proj_kernel(const float* __restrict__ W, const float* __restrict__ bias,
                                const float* __restrict__ resid) {
    int row0 = blockIdx.y * BM, col0 = blockIdx.x * BN;
    float acc[4][4] = {};
    gemm_core<true>(g_ctx, EE, W, EE, EE, row0, col0, nullptr, TOK, acc);
    int tx = threadIdx.x & 15, ty = threadIdx.x >> 4;
    #pragma unroll
    for (int i = 0; i < 4; i++) {
        int r = row0 + ty * 4 + i;
        #pragma unroll
        for (int j = 0; j < 4; j++) {
            int c = col0 + tx * 4 + j;
            g_x[(size_t)r * EE + c] = acc[i][j] + bias[c] + resid[(size_t)r * EE + c];
        }
    }
}

// ---------------- flash attention (64q x 64k tiles, fp32) ----------------
#define ATTN_SMEM (4 * 64 * 68 * 4)   // Qt, Kt, Vs, Pt : 69632 bytes

__global__ void attn_kernel() {
    extern __shared__ float sm[];
    float (*Qt)[68] = (float(*)[68])(sm);                  // [d][q]
    float (*Kt)[68] = (float(*)[68])(sm + 64 * 68);        // [d][k]
    float (*Vs)[68] = (float(*)[68])(sm + 2 * 64 * 68);    // [k][d]
    float (*Pt)[68] = (float(*)[68])(sm + 3 * 64 * 68);    // [k][q]

    int bh = blockIdx.y;
    int b = bh >> 4, h = bh & 15;
    int q0 = blockIdx.x * 64;
    int tid = threadIdx.x, tx = tid & 15, ty = tid >> 4;

    #pragma unroll
    for (int i = 0; i < 16; i++) {
        int id = tid + i * 256;
        int r = id >> 6, c = id & 63;
        Qt[c][r] = g_qp[((size_t)(q0 + r) * NB + b) * EE + h * HD + c] * 0.125f;
    }

    float m[4], l[4], acc[4][4];
    #pragma unroll
    for (int i = 0; i < 4; i++) {
        m[i] = -1e30f; l[i] = 0.f;
        #pragma unroll
        for (int j = 0; j < 4; j++) acc[i][j] = 0.f;
    }
    __syncthreads();

    for (int n0 = 0; n0 < SQ; n0 += 64) {
        #pragma unroll
        for (int i = 0; i < 16; i++) {
            int id = tid + i * 256;
            int r = id >> 6, c = id & 63;
            size_t base = ((size_t)(n0 + r) * NB + b) * EE + h * HD + c;
            Kt[c][r] = g_kp[base];
            Vs[r][c] = g_vp[base];
        }
        __syncthreads();

        // scores S = (Q/8) @ K^T : per-thread 4x4
        float s[4][4] = {};
        #pragma unroll
        for (int d = 0; d < 64; d++) {
            float4 q4 = *reinterpret_cast<const float4*>(&Qt[d][ty * 4]);
            float4 k4 = *reinterpret_cast<const float4*>(&Kt[d][tx * 4]);
            float qv[4] = {q4.x, q4.y, q4.z, q4.w};
            float kv[4] = {k4.x, k4.y, k4.z, k4.w};
            #pragma unroll
            for (int i = 0; i < 4; i++)
                #pragma unroll
                for (int j = 0; j < 4; j++)
                    s[i][j] = fmaf(qv[i], kv[j], s[i][j]);
        }

        // online softmax (row groups share ty; reduce over tx via 16-lane shuffles)
        #pragma unroll
        for (int i = 0; i < 4; i++) {
            float rm = fmaxf(fmaxf(s[i][0], s[i][1]), fmaxf(s[i][2], s[i][3]));
            #pragma unroll
            for (int o = 8; o > 0; o >>= 1) rm = fmaxf(rm, __shfl_xor_sync(0xffffffffu, rm, o));
            float nm = fmaxf(m[i], rm);
            float scale = expf(m[i] - nm);
            float rs = 0.f;
            #pragma unroll
            for (int j = 0; j < 4; j++) { float p = expf(s[i][j] - nm); s[i][j] = p; rs += p; }
            #pragma unroll
            for (int o = 8; o > 0; o >>= 1) rs += __shfl_xor_sync(0xffffffffu, rs, o);
            l[i] = l[i] * scale + rs;
            m[i] = nm;
            #pragma unroll
            for (int j = 0; j < 4; j++) acc[i][j] *= scale;
        }

        // write P transposed [k][q]
        #pragma unroll
        for (int j = 0; j < 4; j++) {
            float4 pv = make_float4(s[0][j], s[1][j], s[2][j], s[3][j]);
            *reinterpret_cast<float4*>(&Pt[tx * 4 + j][ty * 4]) = pv;
        }
        __syncthreads();

        // acc += P @ V
        #pragma unroll
        for (int n = 0; n < 64; n++) {
            float4 p4 = *reinterpret_cast<const float4*>(&Pt[n][ty * 4]);
            float4 v4 = *reinterpret_cast<const float4*>(&Vs[n][tx * 4]);
            float pv[4] = {p4.x, p4.y, p4.z, p4.w};
            float vv[4] = {v4.x, v4.y, v4.z, v4.w};
            #pragma unroll
            for (int i = 0; i < 4; i++)
                #pragma unroll
                for (int j = 0; j < 4; j++)
                    acc[i][j] = fmaf(pv[i], vv[j], acc[i][j]);
        }
        __syncthreads();
    }

    #pragma unroll
    for (int i = 0; i < 4; i++) {
        float inv_l = 1.0f / l[i];
        #pragma unroll
        for (int j = 0; j < 4; j++)
            g_ctx[((size_t)(q0 + ty * 4 + i) * NB + b) * EE + h * HD + tx * 4 + j] = acc[i][j] * inv_l;
    }
}

// ---------------- router: logits = xn @ router_w, argmax ----------------
__global__ void router_kernel(const float* __restrict__ rw) {
    int t = blockIdx.x;
    const float* x = g_xn + (size_t)t * EE;
    float a[NEXP];
    #pragma unroll
    for (int e = 0; e < NEXP; e++) a[e] = 0.f;
    for (int k = threadIdx.x; k < EE; k += 256) {
        float xv = x[k];
        #pragma unroll
        for (int e = 0; e < NEXP; e++) a[e] += xv * rw[k * NEXP + e];
    }
    __shared__ float red[8][NEXP];
    #pragma unroll
    for (int e = 0; e < NEXP; e++) {
        float v = a[e];
        #pragma unroll
        for (int o = 16; o > 0; o >>= 1) v += __shfl_xor_sync(0xffffffffu, v, o);
        if ((threadIdx.x & 31) == 0) red[threadIdx.x >> 5][e] = v;
    }
    __syncthreads();
    if (threadIdx.x == 0) {
        int best = 0; float bv = -1e30f;
        #pragma unroll
        for (int e = 0; e < NEXP; e++) {
            float sum = 0.f;
            #pragma unroll
            for (int w = 0; w < 8; w++) sum += red[w][e];
            if (sum > bv) { bv = sum; best = e; }
        }
        g_eid[t] = best;
    }
}

// ---------------- capacity: sequential per-expert scan (Switch semantics) ----------------
__global__ void capacity_kernel() {
    int e = threadIdx.x;
    if (e >= NEXP) return;
    int cnt = 0;
    for (int t = 0; t < TOK; t++) {
        if (g_eid[t] == e && cnt < CAPN) {
            g_list[e * CAPN + cnt] = t;
            cnt++;
        }
    }
    g_cnt[e] = cnt;
}

// ---------------- MoE GEMM1: H = gelu(gather(xn) @ wi[e]) ----------------
__global__ void moe1_kernel(const float* __restrict__ wi) {
    int e = blockIdx.z;
    int cnt = g_cnt[e];
    int row0 = blockIdx.y * BM;
    if (row0 >= cnt) return;
    int col0 = blockIdx.x * BN;
    float acc[4][4] = {};
    gemm_core<false>(g_xn, EE, wi + (size_t)e * EE * FF, FF, EE, row0, col0,
                     g_list + e * CAPN, cnt, acc);
    int tx = threadIdx.x & 15, ty = threadIdx.x >> 4;
    #pragma unroll
    for (int i = 0; i < 4; i++) {
        int r = row0 + ty * 4 + i;
        if (r < cnt) {
            #pragma unroll
            for (int j = 0; j < 4; j++) {
                float xv = acc[i][j];
                float gv = 0.5f * xv * (1.0f + erff(xv * 0.70710678118654752f));
                g_h[((size_t)e * CAPN + r) * FF + col0 + tx * 4 + j] = gv;
            }
        }
    }
}

// ---------------- init output with residual ----------------
__global__ void init_out_kernel(float* __restrict__ out) {
    int i = blockIdx.x * blockDim.x + threadIdx.x;
    out[i] = g_x[i];
}

// ---------------- MoE GEMM2: out[token] += H @ wo[e] ----------------
__global__ void moe2_kernel(const float* __restrict__ wo, float* __restrict__ out) {
    int e = blockIdx.z;
    int cnt = g_cnt[e];
    int row0 = blockIdx.y * BM;
    if (row0 >= cnt) return;
    int col0 = blockIdx.x * BN;
    float acc[4][4] = {};
    gemm_core<false>(g_h + (size_t)e * CAPN * FF, FF, wo + (size_t)e * FF * EE, EE, FF,
                     row0, col0, nullptr, cnt, acc);
    int tx = threadIdx.x & 15, ty = threadIdx.x >> 4;
    #pragma unroll
    for (int i = 0; i < 4; i++) {
        int r = row0 + ty * 4 + i;
        if (r < cnt) {
            int tok = g_list[e * CAPN + r];
            #pragma unroll
            for (int j = 0; j < 4; j++) {
                size_t o = (size_t)tok * EE + col0 + tx * 4 + j;
                out[o] += acc[i][j];   // unique writer per (token, col)
            }
        }
    }
}

// ---------------- launch ----------------
extern "C" void kernel_launch(void* const* d_in, const int* in_sizes, int n_in,
                              void* d_out, int out_size) {
    const float* q     = (const float*)d_in[0];
    const float* k     = (const float*)d_in[1];
    const float* v     = (const float*)d_in[2];
    const float* in_w  = (const float*)d_in[3];
    const float* in_b  = (const float*)d_in[4];
    const float* out_w = (const float*)d_in[5];
    const float* out_b = (const float*)d_in[6];
    const float* n1s   = (const float*)d_in[7];
    const float* n1b   = (const float*)d_in[8];
    const float* n2s   = (const float*)d_in[9];
    const float* n2b   = (const float*)d_in[10];
    const float* rw    = (const float*)d_in[11];
    const float* wi    = (const float*)d_in[12];
    const float* wo    = (const float*)d_in[13];
    float* out = (float*)d_out;

    cudaFuncSetAttribute(attn_kernel, cudaFuncAttributeMaxDynamicSharedMemorySize, ATTN_SMEM);

    ln1_rope_kernel<<<dim3(TOK, 3), 256>>>(q, k, v, n1s, n1b);
    qkv_proj_kernel<<<dim3(EE / BN, TOK / BM, 3), 256>>>(in_w, in_b);
    attn_kernel<<<dim3(SQ / 64, NB * NH), 256, ATTN_SMEM>>>();
    out_proj_kernel<<<dim3(EE / BN, TOK / BM), 256>>>(out_w, out_b, q);
    ln2_kernel<<<TOK, 256>>>(n2s, n2b);
    router_kernel<<<TOK, 256>>>(rw);
    capacity_kernel<<<1, 32>>>();
    moe1_kernel<<<dim3(FF / BN, CAPN / BM, NEXP), 256>>>(wi);
    init_out_kernel<<<(TOK * EE) / 256, 256>>>(out);
    moe2_kernel<<<dim3(EE / BN, CAPN / BM, NEXP), 256>>>(wo, out);
}

// round 2
// speedup vs baseline: 1.6053x; 1.6053x over previous
#include <cuda_runtime.h>
#include <math.h>
#include <stdint.h>

// ---------------- problem constants ----------------
#define SQ   2048
#define NB   4
#define EE   1024
#define FF   4096
#define NEXP 8
#define CAPN 2048
#define NH   16
#define HD   64
#define TOK  (SQ*NB)          // 8192 tokens

// ---------------- scratch (device globals; no allocation allowed) ----------------
__device__ float g_qn[TOK*EE];
__device__ float g_kn[TOK*EE];
__device__ float g_vn[TOK*EE];
__device__ float g_qp[TOK*EE];
__device__ float g_kp[TOK*EE];
__device__ float g_vp[TOK*EE];
__device__ float g_ctx[TOK*EE];
__device__ float g_x[TOK*EE];          // residual after attention
__device__ float g_xn[TOK*EE];         // LN2 output
__device__ float g_h[(size_t)NEXP*CAPN*FF];   // expert hidden activations
__device__ int   g_eid[TOK];
__device__ int   g_list[NEXP*CAPN];
__device__ int   g_cnt[NEXP];

// ---------------- tf32 helpers ----------------
__device__ __forceinline__ float tf32_rna(float x) {
    uint32_t u;
    asm("cvt.rna.tf32.f32 %0, %1;" : "=r"(u) : "f"(x));
    return __uint_as_float(u);
}
__device__ __forceinline__ void split2(float x, float& h, float& l) {
    h = tf32_rna(x);
    l = tf32_rna(x - h);
}
// D += A*B  (m16n8k8 tf32, row.col)
__device__ __forceinline__ void mma8(float* d, const float* a, const float* b) {
    asm volatile(
        "mma.sync.aligned.m16n8k8.row.col.f32.tf32.tf32.f32 "
        "{%0,%1,%2,%3}, {%4,%5,%6,%7}, {%8,%9}, {%0,%1,%2,%3};"
        : "+f"(d[0]), "+f"(d[1]), "+f"(d[2]), "+f"(d[3])
        : "r"(__float_as_uint(a[0])), "r"(__float_as_uint(a[1])),
          "r"(__float_as_uint(a[2])), "r"(__float_as_uint(a[3])),
          "r"(__float_as_uint(b[0])), "r"(__float_as_uint(b[1])));
}

// ---------------- block reduction helper ----------------
__device__ __forceinline__ float blk_sum256(float v) {
    __shared__ float red[8];
    #pragma unroll
    for (int o = 16; o > 0; o >>= 1) v += __shfl_xor_sync(0xffffffffu, v, o);
    if ((threadIdx.x & 31) == 0) red[threadIdx.x >> 5] = v;
    __syncthreads();
    float s = 0.f;
    #pragma unroll
    for (int i = 0; i < 8; i++) s += red[i];
    __syncthreads();
    return s;
}

// ---------------- LN (+ optional RoPE) ----------------
__device__ __forceinline__ void ln_rope_body(const float* __restrict__ x,
                                             float* __restrict__ o,
                                             const float* __restrict__ sc,
                                             const float* __restrict__ bi,
                                             int srow, int do_rope) {
    float s = 0.f;
    for (int i = threadIdx.x; i < EE; i += 256) s += x[i];
    float mean = blk_sum256(s) * (1.0f / EE);
    float vs = 0.f;
    for (int i = threadIdx.x; i < EE; i += 256) { float d = x[i] - mean; vs += d * d; }
    float var = blk_sum256(vs) * (1.0f / EE);
    float rstd = rsqrtf(var + 1e-5f);
    if (do_rope) {
        for (int i = threadIdx.x; i < EE / 2; i += 256) {
            float x1 = (x[i]       - mean) * rstd * sc[i]       + bi[i];
            float x2 = (x[i + 512] - mean) * rstd * sc[i + 512] + bi[i + 512];
            float inv = (float)(1.0 / pow(10000.0, (double)i * (1.0 / 512.0)));
            float fr = (float)srow * inv;
            float sn, cs;
            sincosf(fr, &sn, &cs);
            o[i]       = x1 * cs - x2 * sn;
            o[i + 512] = x1 * sn + x2 * cs;
        }
    } else {
        for (int i = threadIdx.x; i < EE; i += 256)
            o[i] = (x[i] - mean) * rstd * sc[i] + bi[i];
    }
}

__global__ void ln1_rope_kernel(const float* __restrict__ q, const float* __restrict__ k,
                                const float* __restrict__ v,
                                const float* __restrict__ sc, const float* __restrict__ bi) {
    int z = blockIdx.y;
    const float* in = (z == 0) ? q : (z == 1) ? k : v;
    float* out = (z == 0) ? g_qn : (z == 1) ? g_kn : g_vn;
    int t = blockIdx.x;
    ln_rope_body(in + (size_t)t * EE, out + (size_t)t * EE, sc, bi, t / NB, 1);
}

__global__ void ln2_kernel(const float* __restrict__ sc, const float* __restrict__ bi) {
    int t = blockIdx.x;
    ln_rope_body(g_x + (size_t)t * EE, g_xn + (size_t)t * EE, sc, bi, 0, 0);
}

// ================= tf32 tensor-core GEMM core =================
// Block 128x128, K-step 16, 256 threads = 8 warps (4 in M x 2 in N),
// warp tile 32x64 (2 m-tiles x 8 n-tiles of m16n8k8).
// PLANES==3: 3xTF32 error compensated; PLANES==1: plain tf32.
// BT==true : B stored [N,K] row-major. BT==false: B stored [K,N] row-major.
template<int PLANES, bool BT>
__device__ __forceinline__ void gemm_tc_core(
    const float* __restrict__ A, int lda,
    const float* __restrict__ B, int ldb,
    int K, int row0, int col0,
    const int* __restrict__ gather, int valid,
    float acc[2][8][4])
{
    __shared__ float Ah[128][20];
    __shared__ float Al[128][20];
    __shared__ float Bh[128][20];
    __shared__ float Bl[128][20];

    const int tid  = threadIdx.x;
    const int warp = tid >> 5, lane = tid & 31;
    const int wm = (warp & 3) * 32;
    const int wn = (warp >> 2) * 64;
    const int g  = lane >> 2, tq = lane & 3;

    int arow[2];
    #pragma unroll
    for (int i = 0; i < 2; i++) {
        int r = (tid + i * 256) >> 2;
        int gr = row0 + r;
        if (gr >= valid) gr = valid - 1;
        arow[i] = gather ? gather[gr] : gr;
    }

    for (int k0 = 0; k0 < K; k0 += 16) {
        __syncthreads();
        // ---- load A tile (128x16) ----
        #pragma unroll
        for (int i = 0; i < 2; i++) {
            int id = tid + i * 256;
            int r = id >> 2, q = (id & 3) * 4;
            float4 v = *reinterpret_cast<const float4*>(&A[(size_t)arow[i] * lda + k0 + q]);
            float4 h, l;
            split2(v.x, h.x, l.x); split2(v.y, h.y, l.y);
            split2(v.z, h.z, l.z); split2(v.w, h.w, l.w);
            *reinterpret_cast<float4*>(&Ah[r][q]) = h;
            if (PLANES == 3) *reinterpret_cast<float4*>(&Al[r][q]) = l;
        }
        // ---- load B tile into Bs[n][k] ----
        if (BT) {
            #pragma unroll
            for (int i = 0; i < 2; i++) {
                int id = tid + i * 256;
                int r = id >> 2, q = (id & 3) * 4;
                float4 v = *reinterpret_cast<const float4*>(
                    &B[(size_t)(col0 + r) * ldb + k0 + q]);
                float4 h, l;
                split2(v.x, h.x, l.x); split2(v.y, h.y, l.y);
                split2(v.z, h.z, l.z); split2(v.w, h.w, l.w);
                *reinterpret_cast<float4*>(&Bh[r][q]) = h;
                if (PLANES == 3) *reinterpret_cast<float4*>(&Bl[r][q]) = l;
            }
        } else {
            #pragma unroll
            for (int i = 0; i < 2; i++) {
                int id = tid + i * 256;
                int n = id & 127, kb = (id >> 7) * 4;
                float vj[4];
                #pragma unroll
                for (int j = 0; j < 4; j++)
                    vj[j] = B[(size_t)(k0 + kb + j) * ldb + col0 + n];
                float4 h, l;
                split2(vj[0], h.x, l.x); split2(vj[1], h.y, l.y);
                split2(vj[2], h.z, l.z); split2(vj[3], h.w, l.w);
                *reinterpret_cast<float4*>(&Bh[n][kb]) = h;
                if (PLANES == 3) *reinterpret_cast<float4*>(&Bl[n][kb]) = l;
            }
        }
        __syncthreads();

        // ---- mma ----
        #pragma unroll
        for (int ks = 0; ks < 2; ks++) {
            int kk = ks * 8 + tq;
            float ah[2][4], al[2][4];
            #pragma unroll
            for (int mt = 0; mt < 2; mt++) {
                int r = wm + mt * 16 + g;
                ah[mt][0] = Ah[r][kk];     ah[mt][1] = Ah[r + 8][kk];
                ah[mt][2] = Ah[r][kk + 4]; ah[mt][3] = Ah[r + 8][kk + 4];
                if (PLANES == 3) {
                    al[mt][0] = Al[r][kk];     al[mt][1] = Al[r + 8][kk];
                    al[mt][2] = Al[r][kk + 4]; al[mt][3] = Al[r + 8][kk + 4];
                }
            }
            #pragma unroll
            for (int nt = 0; nt < 8; nt++) {
                int n = wn + nt * 8 + g;
                float bh[2] = { Bh[n][kk], Bh[n][kk + 4] };
                if (PLANES == 3) {
                    float bl[2] = { Bl[n][kk], Bl[n][kk + 4] };
                    #pragma unroll
                    for (int mt = 0; mt < 2; mt++) {
                        mma8(acc[mt][nt], ah[mt], bl);
                        mma8(acc[mt][nt], al[mt], bh);
                    }
                }
                #pragma unroll
                for (int mt = 0; mt < 2; mt++)
                    mma8(acc[mt][nt], ah[mt], bh);
            }
        }
    }
}

// ---------------- QKV projection (3xTF32): C = A @ W^T + b ----------------
__global__ __launch_bounds__(256, 2) void qkv_tc_kernel(const float* __restrict__ W,
                                                        const float* __restrict__ bias) {
    int z = blockIdx.z;
    const float* A = (z == 0) ? g_qn : (z == 1) ? g_kn : g_vn;
    float* C = (z == 0) ? g_qp : (z == 1) ? g_kp : g_vp;
    int row0 = blockIdx.y * 128, col0 = blockIdx.x * 128;
    float acc[2][8][4];
    #pragma unroll
    for (int a = 0; a < 2; a++)
        #pragma unroll
        for (int b = 0; b < 8; b++)
            #pragma unroll
            for (int c = 0; c < 4; c++) acc[a][b][c] = 0.f;
    gemm_tc_core<3, true>(A, EE, W + (size_t)z * EE * EE, EE, EE, row0, col0, nullptr, TOK, acc);

    int warp = threadIdx.x >> 5, lane = threadIdx.x & 31;
    int wm = (warp & 3) * 32, wn = (warp >> 2) * 64;
    int g = lane >> 2, tq = lane & 3;
    #pragma unroll
    for (int mt = 0; mt < 2; mt++) {
        int r = row0 + wm + mt * 16 + g;
        #pragma unroll
        for (int nt = 0; nt < 8; nt++) {
            int c = col0 + wn + nt * 8 + tq * 2;
            float b0 = bias[z * EE + c], b1 = bias[z * EE + c + 1];
            float2 v0 = make_float2(acc[mt][nt][0] + b0, acc[mt][nt][1] + b1);
            float2 v1 = make_float2(acc[mt][nt][2] + b0, acc[mt][nt][3] + b1);
            *reinterpret_cast<float2*>(&C[(size_t)r * EE + c]) = v0;
            *reinterpret_cast<float2*>(&C[(size_t)(r + 8) * EE + c]) = v1;
        }
    }
}

// ---------------- out projection (3xTF32) + bias + residual ----------------
__global__ __launch_bounds__(256, 2) void outproj_tc_kernel(const float* __restrict__ W,
                                                            const float* __restrict__ bias,
                                                            const float* __restrict__ resid) {
    int row0 = blockIdx.y * 128, col0 = blockIdx.x * 128;
    float acc[2][8][4];
    #pragma unroll
    for (int a = 0; a < 2; a++)
        #pragma unroll
        for (int b = 0; b < 8; b++)
            #pragma unroll
            for (int c = 0; c < 4; c++) acc[a][b][c] = 0.f;
    gemm_tc_core<3, true>(g_ctx, EE, W, EE, EE, row0, col0, nullptr, TOK, acc);

    int warp = threadIdx.x >> 5, lane = threadIdx.x & 31;
    int wm = (warp & 3) * 32, wn = (warp >> 2) * 64;
    int g = lane >> 2, tq = lane & 3;
    #pragma unroll
    for (int mt = 0; mt < 2; mt++) {
        int r = row0 + wm + mt * 16 + g;
        #pragma unroll
        for (int nt = 0; nt < 8; nt++) {
            int c = col0 + wn + nt * 8 + tq * 2;
            float b0 = bias[c], b1 = bias[c + 1];
            size_t i0 = (size_t)r * EE + c, i1 = (size_t)(r + 8) * EE + c;
            g_x[i0]     = acc[mt][nt][0] + b0 + resid[i0];
            g_x[i0 + 1] = acc[mt][nt][1] + b1 + resid[i0 + 1];
            g_x[i1]     = acc[mt][nt][2] + b0 + resid[i1];
            g_x[i1 + 1] = acc[mt][nt][3] + b1 + resid[i1 + 1];
        }
    }
}

// ---------------- flash attention, 3xTF32 mma ----------------
// q-tile 128, kt-tile 64. 256 threads, 8 warps; warp w owns q rows [16w,16w+16).
#define APAD 68
#define ATTN_SMEM_FLOATS (768 * APAD)   // Qh,Ql(128) Kh,Kl(64) Vh,Vl(64) Ph,Pl(128)

__global__ __launch_bounds__(256, 1) void attn_tc_kernel() {
    extern __shared__ float sm[];
    float (*Qh)[APAD] = (float(*)[APAD])(sm);
    float (*Ql)[APAD] = (float(*)[APAD])(sm + 128 * APAD);
    float (*Kh)[APAD] = (float(*)[APAD])(sm + 256 * APAD);
    float (*Kl)[APAD] = (float(*)[APAD])(sm + 320 * APAD);
    float (*Vh)[APAD] = (float(*)[APAD])(sm + 384 * APAD);
    float (*Vl)[APAD] = (float(*)[APAD])(sm + 448 * APAD);
    float (*Ph)[APAD] = (float(*)[APAD])(sm + 512 * APAD);
    float (*Pl)[APAD] = (float(*)[APAD])(sm + 640 * APAD);

    int bh = blockIdx.y;
    int b = bh >> 4, h = bh & 15;
    int q0 = blockIdx.x * 128;
    int tid = threadIdx.x, warp = tid >> 5, lane = tid & 31;
    int g = lane >> 2, tq = lane & 3;
    int qw = warp * 16;

    // load Q tile (128 x 64), scale 1/8, split hi/lo
    #pragma unroll
    for (int i = 0; i < 8; i++) {
        int id = tid + i * 256;
        int r = id >> 4, c4 = (id & 15) * 4;
        float4 v = *reinterpret_cast<const float4*>(
            &g_qp[((size_t)(q0 + r) * NB + b) * EE + h * HD + c4]);
        v.x *= 0.125f; v.y *= 0.125f; v.z *= 0.125f; v.w *= 0.125f;
        float4 hh, ll;
        split2(v.x, hh.x, ll.x); split2(v.y, hh.y, ll.y);
        split2(v.z, hh.z, ll.z); split2(v.w, hh.w, ll.w);
        *reinterpret_cast<float4*>(&Qh[r][c4]) = hh;
        *reinterpret_cast<float4*>(&Ql[r][c4]) = ll;
    }

    float o[8][4];
    #pragma unroll
    for (int nt = 0; nt < 8; nt++)
        #pragma unroll
        for (int j = 0; j < 4; j++) o[nt][j] = 0.f;
    float m0 = -1e30f, m1 = -1e30f, l0 = 0.f, l1 = 0.f;

    for (int n0 = 0; n0 < SQ; n0 += 64) {
        __syncthreads();
        // load K tile (64 x 64) -> Kh[kt][d]
        #pragma unroll
        for (int i = 0; i < 4; i++) {
            int id = tid + i * 256;
            int r = id >> 4, c4 = (id & 15) * 4;
            float4 v = *reinterpret_cast<const float4*>(
                &g_kp[((size_t)(n0 + r) * NB + b) * EE + h * HD + c4]);
            float4 hh, ll;
            split2(v.x, hh.x, ll.x); split2(v.y, hh.y, ll.y);
            split2(v.z, hh.z, ll.z); split2(v.w, hh.w, ll.w);
            *reinterpret_cast<float4*>(&Kh[r][c4]) = hh;
            *reinterpret_cast<float4*>(&Kl[r][c4]) = ll;
        }
        // load V tile transposed -> Vh[d][kt]
        #pragma unroll
        for (int i = 0; i < 4; i++) {
            int id = tid + i * 256;
            int d = id & 63, kt = (id >> 6) * 4;
            float4 hh, ll;
            float vj[4];
            #pragma unroll
            for (int j = 0; j < 4; j++)
                vj[j] = g_vp[((size_t)(n0 + kt + j) * NB + b) * EE + h * HD + d];
            split2(vj[0], hh.x, ll.x); split2(vj[1], hh.y, ll.y);
            split2(vj[2], hh.z, ll.z); split2(vj[3], hh.w, ll.w);
            *reinterpret_cast<float4*>(&Vh[d][kt]) = hh;
            *reinterpret_cast<float4*>(&Vl[d][kt]) = ll;
        }
        __syncthreads();

        // ---- S = Q @ K^T (3xTF32) ----
        float s[8][4];
        #pragma unroll
        for (int nt = 0; nt < 8; nt++)
            #pragma unroll
            for (int j = 0; j < 4; j++) s[nt][j] = 0.f;

        #pragma unroll
        for (int ks = 0; ks < 8; ks++) {
            int kk = ks * 8 + tq;
            int r = qw + g;
            float ah[4] = { Qh[r][kk], Qh[r + 8][kk], Qh[r][kk + 4], Qh[r + 8][kk + 4] };
            float al[4] = { Ql[r][kk], Ql[r + 8][kk], Ql[r][kk + 4], Ql[r + 8][kk + 4] };
            #pragma unroll
            for (int nt = 0; nt < 8; nt++) {
                int n = nt * 8 + g;
                float bh[2] = { Kh[n][kk], Kh[n][kk + 4] };
                float bl[2] = { Kl[n][kk], Kl[n][kk + 4] };
                mma8(s[nt], ah, bl);
                mma8(s[nt], al, bh);
                mma8(s[nt], ah, bh);
            }
        }

        // ---- online softmax (rows r=qw+g and r+8; reduce over 4 lanes) ----
        float rm0 = -1e30f, rm1 = -1e30f;
        #pragma unroll
        for (int nt = 0; nt < 8; nt++) {
            rm0 = fmaxf(rm0, fmaxf(s[nt][0], s[nt][1]));
            rm1 = fmaxf(rm1, fmaxf(s[nt][2], s[nt][3]));
        }
        rm0 = fmaxf(rm0, __shfl_xor_sync(0xffffffffu, rm0, 1));
        rm0 = fmaxf(rm0, __shfl_xor_sync(0xffffffffu, rm0, 2));
        rm1 = fmaxf(rm1, __shfl_xor_sync(0xffffffffu, rm1, 1));
        rm1 = fmaxf(rm1, __shfl_xor_sync(0xffffffffu, rm1, 2));
        float nm0 = fmaxf(m0, rm0), nm1 = fmaxf(m1, rm1);
        float c0 = __expf(m0 - nm0), c1 = __expf(m1 - nm1);
        float sum0 = 0.f, sum1 = 0.f;
        #pragma unroll
        for (int nt = 0; nt < 8; nt++) {
            s[nt][0] = __expf(s[nt][0] - nm0); sum0 += s[nt][0];
            s[nt][1] = __expf(s[nt][1] - nm0); sum0 += s[nt][1];
            s[nt][2] = __expf(s[nt][2] - nm1); sum1 += s[nt][2];
            s[nt][3] = __expf(s[nt][3] - nm1); sum1 += s[nt][3];
        }
        sum0 += __shfl_xor_sync(0xffffffffu, sum0, 1);
        sum0 += __shfl_xor_sync(0xffffffffu, sum0, 2);
        sum1 += __shfl_xor_sync(0xffffffffu, sum1, 1);
        sum1 += __shfl_xor_sync(0xffffffffu, sum1, 2);
        l0 = l0 * c0 + sum0; l1 = l1 * c1 + sum1;
        m0 = nm0; m1 = nm1;
        #pragma unroll
        for (int nt = 0; nt < 8; nt++) {
            o[nt][0] *= c0; o[nt][1] *= c0;
            o[nt][2] *= c1; o[nt][3] *= c1;
        }

        // ---- stage P (split hi/lo) into smem, per-warp private rows ----
        #pragma unroll
        for (int nt = 0; nt < 8; nt++) {
            int c = nt * 8 + tq * 2;
            int r = qw + g;
            float h0, lo0, h1, lo1;
            split2(s[nt][0], h0, lo0); split2(s[nt][1], h1, lo1);
            *reinterpret_cast<float2*>(&Ph[r][c]) = make_float2(h0, h1);
            *reinterpret_cast<float2*>(&Pl[r][c]) = make_float2(lo0, lo1);
            split2(s[nt][2], h0, lo0); split2(s[nt][3], h1, lo1);
            *reinterpret_cast<float2*>(&Ph[r + 8][c]) = make_float2(h0, h1);
            *reinterpret_cast<float2*>(&Pl[r + 8][c]) = make_float2(lo0, lo1);
        }
        __syncwarp();

        // ---- O += P @ V (3xTF32) ----
        #pragma unroll
        for (int ks = 0; ks < 8; ks++) {
            int kk = ks * 8 + tq;
            int r = qw + g;
            float ah[4] = { Ph[r][kk], Ph[r + 8][kk], Ph[r][kk + 4], Ph[r + 8][kk + 4] };
            float al[4] = { Pl[r][kk], Pl[r + 8][kk], Pl[r][kk + 4], Pl[r + 8][kk + 4] };
            #pragma unroll
            for (int nt = 0; nt < 8; nt++) {
                int n = nt * 8 + g;
                float bh[2] = { Vh[n][kk], Vh[n][kk + 4] };
                float bl[2] = { Vl[n][kk], Vl[n][kk + 4] };
                mma8(o[nt], ah, bl);
                mma8(o[nt], al, bh);
                mma8(o[nt], ah, bh);
            }
        }
    }

    // ---- epilogue ----
    float inv0 = 1.0f / l0, inv1 = 1.0f / l1;
    int r0 = q0 + qw + g, r1 = r0 + 8;
    #pragma unroll
    for (int nt = 0; nt < 8; nt++) {
        int d = nt * 8 + tq * 2;
        *reinterpret_cast<float2*>(&g_ctx[((size_t)r0 * NB + b) * EE + h * HD + d]) =
            make_float2(o[nt][0] * inv0, o[nt][1] * inv0);
        *reinterpret_cast<float2*>(&g_ctx[((size_t)r1 * NB + b) * EE + h * HD + d]) =
            make_float2(o[nt][2] * inv1, o[nt][3] * inv1);
    }
}

// ---------------- router: logits = xn @ router_w, argmax ----------------
__global__ void router_kernel(const float* __restrict__ rw) {
    int t = blockIdx.x;
    const float* x = g_xn + (size_t)t * EE;
    float a[NEXP];
    #pragma unroll
    for (int e = 0; e < NEXP; e++) a[e] = 0.f;
    for (int k = threadIdx.x; k < EE; k += 256) {
        float xv = x[k];
        #pragma unroll
        for (int e = 0; e < NEXP; e++) a[e] += xv * rw[k * NEXP + e];
    }
    __shared__ float red[8][NEXP];
    #pragma unroll
    for (int e = 0; e < NEXP; e++) {
        float v = a[e];
        #pragma unroll
        for (int o = 16; o > 0; o >>= 1) v += __shfl_xor_sync(0xffffffffu, v, o);
        if ((threadIdx.x & 31) == 0) red[threadIdx.x >> 5][e] = v;
    }
    __syncthreads();
    if (threadIdx.x == 0) {
        int best = 0; float bv = -1e30f;
        #pragma unroll
        for (int e = 0; e < NEXP; e++) {
            float sum = 0.f;
            #pragma unroll
            for (int w = 0; w < 8; w++) sum += red[w][e];
            if (sum > bv) { bv = sum; best = e; }
        }
        g_eid[t] = best;
    }
}

// ---------------- capacity: sequential per-expert scan ----------------
__global__ void capacity_kernel() {
    int e = threadIdx.x;
    if (e >= NEXP) return;
    int cnt = 0;
    for (int t = 0; t < TOK; t++) {
        if (g_eid[t] == e && cnt < CAPN) {
            g_list[e * CAPN + cnt] = t;
            cnt++;
        }
    }
    g_cnt[e] = cnt;
}

// ---------------- MoE GEMM1 (1xTF32): H = gelu(gather(xn) @ wi[e]) ----------------
__global__ __launch_bounds__(256, 2) void moe1_tc_kernel(const float* __restrict__ wi) {
    int e = blockIdx.z;
    int cnt = g_cnt[e];
    int row0 = blockIdx.y * 128;
    if (row0 >= cnt) return;
    int col0 = blockIdx.x * 128;
    float acc[2][8][4];
    #pragma unroll
    for (int a = 0; a < 2; a++)
        #pragma unroll
        for (int b = 0; b < 8; b++)
            #pragma unroll
            for (int c = 0; c < 4; c++) acc[a][b][c] = 0.f;
    gemm_tc_core<1, false>(g_xn, EE, wi + (size_t)e * EE * FF, FF, EE, row0, col0,
                           g_list + e * CAPN, cnt, acc);

    int warp = threadIdx.x >> 5, lane = threadIdx.x & 31;
    int wm = (warp & 3) * 32, wn = (warp >> 2) * 64;
    int g = lane >> 2, tq = lane & 3;
    #pragma unroll
    for (int mt = 0; mt < 2; mt++) {
        #pragma unroll
        for (int p = 0; p < 2; p++) {
            int r = row0 + wm + mt * 16 + g + p * 8;
            if (r < cnt) {
                #pragma unroll
                for (int nt = 0; nt < 8; nt++) {
                    int c = col0 + wn + nt * 8 + tq * 2;
                    float x0 = acc[mt][nt][p * 2], x1 = acc[mt][nt][p * 2 + 1];
                    float g0 = 0.5f * x0 * (1.0f + erff(x0 * 0.70710678118654752f));
                    float g1 = 0.5f * x1 * (1.0f + erff(x1 * 0.70710678118654752f));
                    *reinterpret_cast<float2*>(
                        &g_h[((size_t)e * CAPN + r) * FF + c]) = make_float2(g0, g1);
                }
            }
        }
    }
}

// ---------------- init output with residual ----------------
__global__ void init_out_kernel(float* __restrict__ out) {
    int i = blockIdx.x * blockDim.x + threadIdx.x;
    out[i] = g_x[i];
}

// ---------------- MoE GEMM2 (1xTF32): out[token] += H @ wo[e] ----------------
__global__ __launch_bounds__(256, 2) void moe2_tc_kernel(const float* __restrict__ wo,
                                                         float* __restrict__ out) {
    int e = blockIdx.z;
    int cnt = g_cnt[e];
    int row0 = blockIdx.y * 128;
    if (row0 >= cnt) return;
    int col0 = blockIdx.x * 128;
    float acc[2][8][4];
    #pragma unroll
    for (int a = 0; a < 2; a++)
        #pragma unroll
        for (int b = 0; b < 8; b++)
            #pragma unroll
            for (int c = 0; c < 4; c++) acc[a][b][c] = 0.f;
    gemm_tc_core<1, false>(g_h + (size_t)e * CAPN * FF, FF, wo + (size_t)e * FF * EE, EE,
                           FF, row0, col0, nullptr, cnt, acc);

    int warp = threadIdx.x >> 5, lane = threadIdx.x & 31;
    int wm = (warp & 3) * 32, wn = (warp >> 2) * 64;
    int g = lane >> 2, tq = lane & 3;
    #pragma unroll
    for (int mt = 0; mt < 2; mt++) {
        #pragma unroll
        for (int p = 0; p < 2; p++) {
            int r = row0 + wm + mt * 16 + g + p * 8;
            if (r < cnt) {
                int tok = g_list[e * CAPN + r];
                #pragma unroll
                for (int nt = 0; nt < 8; nt++) {
                    int c = col0 + wn + nt * 8 + tq * 2;
                    size_t i0 = (size_t)tok * EE + c;
                    out[i0]     += acc[mt][nt][p * 2];
                    out[i0 + 1] += acc[mt][nt][p * 2 + 1];
                }
            }
        }
    }
}

// ---------------- launch ----------------
extern "C" void kernel_launch(void* const* d_in, const int* in_sizes, int n_in,
                              void* d_out, int out_size) {
    const float* q     = (const float*)d_in[0];
    const float* k     = (const float*)d_in[1];
    const float* v     = (const float*)d_in[2];
    const float* in_w  = (const float*)d_in[3];
    const float* in_b  = (const float*)d_in[4];
    const float* out_w = (const float*)d_in[5];
    const float* out_b = (const float*)d_in[6];
    const float* n1s   = (const float*)d_in[7];
    const float* n1b   = (const float*)d_in[8];
    const float* n2s   = (const float*)d_in[9];
    const float* n2b   = (const float*)d_in[10];
    const float* rw    = (const float*)d_in[11];
    const float* wi    = (const float*)d_in[12];
    const float* wo    = (const float*)d_in[13];
    float* out = (float*)d_out;

    static int attr_done = 0;
    if (!attr_done) {
        cudaFuncSetAttribute(attn_tc_kernel, cudaFuncAttributeMaxDynamicSharedMemorySize,
                             ATTN_SMEM_FLOATS * 4);
        attr_done = 1;
    }

    ln1_rope_kernel<<<dim3(TOK, 3), 256>>>(q, k, v, n1s, n1b);
    qkv_tc_kernel<<<dim3(EE / 128, TOK / 128, 3), 256>>>(in_w, in_b);
    attn_tc_kernel<<<dim3(SQ / 128, NB * NH), 256, ATTN_SMEM_FLOATS * 4>>>();
    outproj_tc_kernel<<<dim3(EE / 128, TOK / 128), 256>>>(out_w, out_b, q);
    ln2_kernel<<<TOK, 256>>>(n2s, n2b);
    router_kernel<<<TOK, 256>>>(rw);
    capacity_kernel<<<1, 32>>>();
    moe1_tc_kernel<<<dim3(FF / 128, CAPN / 128, NEXP), 256>>>(wi);
    init_out_kernel<<<(TOK * EE) / 256, 256>>>(out);
    moe2_tc_kernel<<<dim3(EE / 128, CAPN / 128, NEXP), 256>>>(wo, out);
}

// round 3
// speedup vs baseline: 1.6084x; 1.0019x over previous
#include <cuda_runtime.h>
#include <math.h>
#include <stdint.h>

// ---------------- problem constants ----------------
#define SQ   2048
#define NB   4
#define EE   1024
#define FF   4096
#define NEXP 8
#define CAPN 2048
#define NH   16
#define HD   64
#define TOK  (SQ*NB)          // 8192 tokens

// ---------------- scratch (device globals; no allocation allowed) ----------------
__device__ float g_qn[TOK*EE];
__device__ float g_kn[TOK*EE];
__device__ float g_vn[TOK*EE];
__device__ float g_qp[TOK*EE];
__device__ float g_kp[TOK*EE];
__device__ float g_vp[TOK*EE];
__device__ float g_ctx[TOK*EE];
__device__ float g_x[TOK*EE];          // residual after attention
__device__ float g_xn[TOK*EE];         // LN2 output
__device__ float g_h[(size_t)NEXP*CAPN*FF];   // expert hidden activations
__device__ int   g_eid[TOK];
__device__ int   g_list[NEXP*CAPN];
__device__ int   g_cnt[NEXP];

// ---------------- tf32 helpers ----------------
__device__ __forceinline__ float tf32_rna(float x) {
    uint32_t u;
    asm("cvt.rna.tf32.f32 %0, %1;" : "=r"(u) : "f"(x));
    return __uint_as_float(u);
}
__device__ __forceinline__ void split2(float x, float& h, float& l) {
    h = tf32_rna(x);
    l = tf32_rna(x - h);
}
// D += A*B  (m16n8k8 tf32, row.col)
__device__ __forceinline__ void mma8(float* d, const float* a, const float* b) {
    asm volatile(
        "mma.sync.aligned.m16n8k8.row.col.f32.tf32.tf32.f32 "
        "{%0,%1,%2,%3}, {%4,%5,%6,%7}, {%8,%9}, {%0,%1,%2,%3};"
        : "+f"(d[0]), "+f"(d[1]), "+f"(d[2]), "+f"(d[3])
        : "r"(__float_as_uint(a[0])), "r"(__float_as_uint(a[1])),
          "r"(__float_as_uint(a[2])), "r"(__float_as_uint(a[3])),
          "r"(__float_as_uint(b[0])), "r"(__float_as_uint(b[1])));
}

// ---------------- block reduction helper ----------------
__device__ __forceinline__ float blk_sum256(float v) {
    __shared__ float red[8];
    #pragma unroll
    for (int o = 16; o > 0; o >>= 1) v += __shfl_xor_sync(0xffffffffu, v, o);
    if ((threadIdx.x & 31) == 0) red[threadIdx.x >> 5] = v;
    __syncthreads();
    float s = 0.f;
    #pragma unroll
    for (int i = 0; i < 8; i++) s += red[i];
    __syncthreads();
    return s;
}

// ---------------- LN (+ optional RoPE) ----------------
__device__ __forceinline__ void ln_rope_body(const float* __restrict__ x,
                                             float* __restrict__ o,
                                             const float* __restrict__ sc,
                                             const float* __restrict__ bi,
                                             int srow, int do_rope) {
    float s = 0.f;
    for (int i = threadIdx.x; i < EE; i += 256) s += x[i];
    float mean = blk_sum256(s) * (1.0f / EE);
    float vs = 0.f;
    for (int i = threadIdx.x; i < EE; i += 256) { float d = x[i] - mean; vs += d * d; }
    float var = blk_sum256(vs) * (1.0f / EE);
    float rstd = rsqrtf(var + 1e-5f);
    if (do_rope) {
        for (int i = threadIdx.x; i < EE / 2; i += 256) {
            float x1 = (x[i]       - mean) * rstd * sc[i]       + bi[i];
            float x2 = (x[i + 512] - mean) * rstd * sc[i + 512] + bi[i + 512];
            float inv = (float)(1.0 / pow(10000.0, (double)i * (1.0 / 512.0)));
            float fr = (float)srow * inv;
            float sn, cs;
            sincosf(fr, &sn, &cs);
            o[i]       = x1 * cs - x2 * sn;
            o[i + 512] = x1 * sn + x2 * cs;
        }
    } else {
        for (int i = threadIdx.x; i < EE; i += 256)
            o[i] = (x[i] - mean) * rstd * sc[i] + bi[i];
    }
}

__global__ void ln1_rope_kernel(const float* __restrict__ q, const float* __restrict__ k,
                                const float* __restrict__ v,
                                const float* __restrict__ sc, const float* __restrict__ bi) {
    int z = blockIdx.y;
    const float* in = (z == 0) ? q : (z == 1) ? k : v;
    float* out = (z == 0) ? g_qn : (z == 1) ? g_kn : g_vn;
    int t = blockIdx.x;
    ln_rope_body(in + (size_t)t * EE, out + (size_t)t * EE, sc, bi, t / NB, 1);
}

__global__ void ln2_kernel(const float* __restrict__ sc, const float* __restrict__ bi) {
    int t = blockIdx.x;
    ln_rope_body(g_x + (size_t)t * EE, g_xn + (size_t)t * EE, sc, bi, 0, 0);
}

// ================= tf32 tensor-core GEMM core =================
// Block 128x128, K-step 16, 256 threads = 8 warps (4 in M x 2 in N),
// warp tile 32x64 (2 m-tiles x 8 n-tiles of m16n8k8).
// PLANES==3: 3xTF32 error compensated; PLANES==1: plain tf32.
// BT==true : B stored [N,K] row-major. BT==false: B stored [K,N] row-major.
template<int PLANES, bool BT>
__device__ __forceinline__ void gemm_tc_core(
    const float* __restrict__ A, int lda,
    const float* __restrict__ B, int ldb,
    int K, int row0, int col0,
    const int* __restrict__ gather, int valid,
    float acc[2][8][4])
{
    __shared__ float Ah[128][20];
    __shared__ float Al[128][20];
    __shared__ float Bh[128][20];
    __shared__ float Bl[128][20];

    const int tid  = threadIdx.x;
    const int warp = tid >> 5, lane = tid & 31;
    const int wm = (warp & 3) * 32;
    const int wn = (warp >> 2) * 64;
    const int g  = lane >> 2, tq = lane & 3;

    int arow[2];
    #pragma unroll
    for (int i = 0; i < 2; i++) {
        int r = (tid + i * 256) >> 2;
        int gr = row0 + r;
        if (gr >= valid) gr = valid - 1;
        arow[i] = gather ? gather[gr] : gr;
    }

    for (int k0 = 0; k0 < K; k0 += 16) {
        __syncthreads();
        // ---- load A tile (128x16) ----
        #pragma unroll
        for (int i = 0; i < 2; i++) {
            int id = tid + i * 256;
            int r = id >> 2, q = (id & 3) * 4;
            float4 v = *reinterpret_cast<const float4*>(&A[(size_t)arow[i] * lda + k0 + q]);
            float4 h, l;
            split2(v.x, h.x, l.x); split2(v.y, h.y, l.y);
            split2(v.z, h.z, l.z); split2(v.w, h.w, l.w);
            *reinterpret_cast<float4*>(&Ah[r][q]) = h;
            if (PLANES == 3) *reinterpret_cast<float4*>(&Al[r][q]) = l;
        }
        // ---- load B tile into Bs[n][k] ----
        if (BT) {
            #pragma unroll
            for (int i = 0; i < 2; i++) {
                int id = tid + i * 256;
                int r = id >> 2, q = (id & 3) * 4;
                float4 v = *reinterpret_cast<const float4*>(
                    &B[(size_t)(col0 + r) * ldb + k0 + q]);
                float4 h, l;
                split2(v.x, h.x, l.x); split2(v.y, h.y, l.y);
                split2(v.z, h.z, l.z); split2(v.w, h.w, l.w);
                *reinterpret_cast<float4*>(&Bh[r][q]) = h;
                if (PLANES == 3) *reinterpret_cast<float4*>(&Bl[r][q]) = l;
            }
        } else {
            #pragma unroll
            for (int i = 0; i < 2; i++) {
                int id = tid + i * 256;
                int n = id & 127, kb = (id >> 7) * 4;
                float vj[4];
                #pragma unroll
                for (int j = 0; j < 4; j++)
                    vj[j] = B[(size_t)(k0 + kb + j) * ldb + col0 + n];
                float4 h, l;
                split2(vj[0], h.x, l.x); split2(vj[1], h.y, l.y);
                split2(vj[2], h.z, l.z); split2(vj[3], h.w, l.w);
                *reinterpret_cast<float4*>(&Bh[n][kb]) = h;
                if (PLANES == 3) *reinterpret_cast<float4*>(&Bl[n][kb]) = l;
            }
        }
        __syncthreads();

        // ---- mma ----
        #pragma unroll
        for (int ks = 0; ks < 2; ks++) {
            int kk = ks * 8 + tq;
            float ah[2][4], al[2][4];
            #pragma unroll
            for (int mt = 0; mt < 2; mt++) {
                int r = wm + mt * 16 + g;
                ah[mt][0] = Ah[r][kk];     ah[mt][1] = Ah[r + 8][kk];
                ah[mt][2] = Ah[r][kk + 4]; ah[mt][3] = Ah[r + 8][kk + 4];
                if (PLANES == 3) {
                    al[mt][0] = Al[r][kk];     al[mt][1] = Al[r + 8][kk];
                    al[mt][2] = Al[r][kk + 4]; al[mt][3] = Al[r + 8][kk + 4];
                }
            }
            #pragma unroll
            for (int nt = 0; nt < 8; nt++) {
                int n = wn + nt * 8 + g;
                float bh[2] = { Bh[n][kk], Bh[n][kk + 4] };
                if (PLANES == 3) {
                    float bl[2] = { Bl[n][kk], Bl[n][kk + 4] };
                    #pragma unroll
                    for (int mt = 0; mt < 2; mt++) {
                        mma8(acc[mt][nt], ah[mt], bl);
                        mma8(acc[mt][nt], al[mt], bh);
                    }
                }
                #pragma unroll
                for (int mt = 0; mt < 2; mt++)
                    mma8(acc[mt][nt], ah[mt], bh);
            }
        }
    }
}

// ---------------- QKV projection (3xTF32): C = A @ W^T + b ----------------
__global__ __launch_bounds__(256, 2) void qkv_tc_kernel(const float* __restrict__ W,
                                                        const float* __restrict__ bias) {
    int z = blockIdx.z;
    const float* A = (z == 0) ? g_qn : (z == 1) ? g_kn : g_vn;
    float* C = (z == 0) ? g_qp : (z == 1) ? g_kp : g_vp;
    int row0 = blockIdx.y * 128, col0 = blockIdx.x * 128;
    float acc[2][8][4];
    #pragma unroll
    for (int a = 0; a < 2; a++)
        #pragma unroll
        for (int b = 0; b < 8; b++)
            #pragma unroll
            for (int c = 0; c < 4; c++) acc[a][b][c] = 0.f;
    gemm_tc_core<3, true>(A, EE, W + (size_t)z * EE * EE, EE, EE, row0, col0, nullptr, TOK, acc);

    int warp = threadIdx.x >> 5, lane = threadIdx.x & 31;
    int wm = (warp & 3) * 32, wn = (warp >> 2) * 64;
    int g = lane >> 2, tq = lane & 3;
    #pragma unroll
    for (int mt = 0; mt < 2; mt++) {
        int r = row0 + wm + mt * 16 + g;
        #pragma unroll
        for (int nt = 0; nt < 8; nt++) {
            int c = col0 + wn + nt * 8 + tq * 2;
            float b0 = bias[z * EE + c], b1 = bias[z * EE + c + 1];
            float2 v0 = make_float2(acc[mt][nt][0] + b0, acc[mt][nt][1] + b1);
            float2 v1 = make_float2(acc[mt][nt][2] + b0, acc[mt][nt][3] + b1);
            *reinterpret_cast<float2*>(&C[(size_t)r * EE + c]) = v0;
            *reinterpret_cast<float2*>(&C[(size_t)(r + 8) * EE + c]) = v1;
        }
    }
}

// ---------------- out projection (3xTF32) + bias + residual ----------------
__global__ __launch_bounds__(256, 2) void outproj_tc_kernel(const float* __restrict__ W,
                                                            const float* __restrict__ bias,
                                                            const float* __restrict__ resid) {
    int row0 = blockIdx.y * 128, col0 = blockIdx.x * 128;
    float acc[2][8][4];
    #pragma unroll
    for (int a = 0; a < 2; a++)
        #pragma unroll
        for (int b = 0; b < 8; b++)
            #pragma unroll
            for (int c = 0; c < 4; c++) acc[a][b][c] = 0.f;
    gemm_tc_core<3, true>(g_ctx, EE, W, EE, EE, row0, col0, nullptr, TOK, acc);

    int warp = threadIdx.x >> 5, lane = threadIdx.x & 31;
    int wm = (warp & 3) * 32, wn = (warp >> 2) * 64;
    int g = lane >> 2, tq = lane & 3;
    #pragma unroll
    for (int mt = 0; mt < 2; mt++) {
        int r = row0 + wm + mt * 16 + g;
        #pragma unroll
        for (int nt = 0; nt < 8; nt++) {
            int c = col0 + wn + nt * 8 + tq * 2;
            float b0 = bias[c], b1 = bias[c + 1];
            size_t i0 = (size_t)r * EE + c, i1 = (size_t)(r + 8) * EE + c;
            g_x[i0]     = acc[mt][nt][0] + b0 + resid[i0];
            g_x[i0 + 1] = acc[mt][nt][1] + b1 + resid[i0 + 1];
            g_x[i1]     = acc[mt][nt][2] + b0 + resid[i1];
            g_x[i1 + 1] = acc[mt][nt][3] + b1 + resid[i1 + 1];
        }
    }
}

// ---------------- flash attention, 3xTF32 mma ----------------
// q-tile 128, kt-tile 64. 256 threads, 8 warps; warp w owns q rows [16w,16w+16).
#define APAD 68
#define ATTN_SMEM_FLOATS (768 * APAD)   // Qh,Ql(128) Kh,Kl(64) Vh,Vl(64) Ph,Pl(128)

__global__ __launch_bounds__(256, 1) void attn_tc_kernel() {
    extern __shared__ float sm[];
    float (*Qh)[APAD] = (float(*)[APAD])(sm);
    float (*Ql)[APAD] = (float(*)[APAD])(sm + 128 * APAD);
    float (*Kh)[APAD] = (float(*)[APAD])(sm + 256 * APAD);
    float (*Kl)[APAD] = (float(*)[APAD])(sm + 320 * APAD);
    float (*Vh)[APAD] = (float(*)[APAD])(sm + 384 * APAD);
    float (*Vl)[APAD] = (float(*)[APAD])(sm + 448 * APAD);
    float (*Ph)[APAD] = (float(*)[APAD])(sm + 512 * APAD);
    float (*Pl)[APAD] = (float(*)[APAD])(sm + 640 * APAD);

    int bh = blockIdx.y;
    int b = bh >> 4, h = bh & 15;
    int q0 = blockIdx.x * 128;
    int tid = threadIdx.x, warp = tid >> 5, lane = tid & 31;
    int g = lane >> 2, tq = lane & 3;
    int qw = warp * 16;

    // load Q tile (128 x 64), scale 1/8, split hi/lo
    #pragma unroll
    for (int i = 0; i < 8; i++) {
        int id = tid + i * 256;
        int r = id >> 4, c4 = (id & 15) * 4;
        float4 v = *reinterpret_cast<const float4*>(
            &g_qp[((size_t)(q0 + r) * NB + b) * EE + h * HD + c4]);
        v.x *= 0.125f; v.y *= 0.125f; v.z *= 0.125f; v.w *= 0.125f;
        float4 hh, ll;
        split2(v.x, hh.x, ll.x); split2(v.y, hh.y, ll.y);
        split2(v.z, hh.z, ll.z); split2(v.w, hh.w, ll.w);
        *reinterpret_cast<float4*>(&Qh[r][c4]) = hh;
        *reinterpret_cast<float4*>(&Ql[r][c4]) = ll;
    }

    float o[8][4];
    #pragma unroll
    for (int nt = 0; nt < 8; nt++)
        #pragma unroll
        for (int j = 0; j < 4; j++) o[nt][j] = 0.f;
    float m0 = -1e30f, m1 = -1e30f, l0 = 0.f, l1 = 0.f;

    for (int n0 = 0; n0 < SQ; n0 += 64) {
        __syncthreads();
        // load K tile (64 x 64) -> Kh[kt][d]
        #pragma unroll
        for (int i = 0; i < 4; i++) {
            int id = tid + i * 256;
            int r = id >> 4, c4 = (id & 15) * 4;
            float4 v = *reinterpret_cast<const float4*>(
                &g_kp[((size_t)(n0 + r) * NB + b) * EE + h * HD + c4]);
            float4 hh, ll;
            split2(v.x, hh.x, ll.x); split2(v.y, hh.y, ll.y);
            split2(v.z, hh.z, ll.z); split2(v.w, hh.w, ll.w);
            *reinterpret_cast<float4*>(&Kh[r][c4]) = hh;
            *reinterpret_cast<float4*>(&Kl[r][c4]) = ll;
        }
        // load V tile transposed -> Vh[d][kt]
        #pragma unroll
        for (int i = 0; i < 4; i++) {
            int id = tid + i * 256;
            int d = id & 63, kt = (id >> 6) * 4;
            float4 hh, ll;
            float vj[4];
            #pragma unroll
            for (int j = 0; j < 4; j++)
                vj[j] = g_vp[((size_t)(n0 + kt + j) * NB + b) * EE + h * HD + d];
            split2(vj[0], hh.x, ll.x); split2(vj[1], hh.y, ll.y);
            split2(vj[2], hh.z, ll.z); split2(vj[3], hh.w, ll.w);
            *reinterpret_cast<float4*>(&Vh[d][kt]) = hh;
            *reinterpret_cast<float4*>(&Vl[d][kt]) = ll;
        }
        __syncthreads();

        // ---- S = Q @ K^T (3xTF32) ----
        float s[8][4];
        #pragma unroll
        for (int nt = 0; nt < 8; nt++)
            #pragma unroll
            for (int j = 0; j < 4; j++) s[nt][j] = 0.f;

        #pragma unroll
        for (int ks = 0; ks < 8; ks++) {
            int kk = ks * 8 + tq;
            int r = qw + g;
            float ah[4] = { Qh[r][kk], Qh[r + 8][kk], Qh[r][kk + 4], Qh[r + 8][kk + 4] };
            float al[4] = { Ql[r][kk], Ql[r + 8][kk], Ql[r][kk + 4], Ql[r + 8][kk + 4] };
            #pragma unroll
            for (int nt = 0; nt < 8; nt++) {
                int n = nt * 8 + g;
                float bh[2] = { Kh[n][kk], Kh[n][kk + 4] };
                float bl[2] = { Kl[n][kk], Kl[n][kk + 4] };
                mma8(s[nt], ah, bl);
                mma8(s[nt], al, bh);
                mma8(s[nt], ah, bh);
            }
        }

        // ---- online softmax (rows r=qw+g and r+8; reduce over 4 lanes) ----
        float rm0 = -1e30f, rm1 = -1e30f;
        #pragma unroll
        for (int nt = 0; nt < 8; nt++) {
            rm0 = fmaxf(rm0, fmaxf(s[nt][0], s[nt][1]));
            rm1 = fmaxf(rm1, fmaxf(s[nt][2], s[nt][3]));
        }
        rm0 = fmaxf(rm0, __shfl_xor_sync(0xffffffffu, rm0, 1));
        rm0 = fmaxf(rm0, __shfl_xor_sync(0xffffffffu, rm0, 2));
        rm1 = fmaxf(rm1, __shfl_xor_sync(0xffffffffu, rm1, 1));
        rm1 = fmaxf(rm1, __shfl_xor_sync(0xffffffffu, rm1, 2));
        float nm0 = fmaxf(m0, rm0), nm1 = fmaxf(m1, rm1);
        float c0 = __expf(m0 - nm0), c1 = __expf(m1 - nm1);
        float sum0 = 0.f, sum1 = 0.f;
        #pragma unroll
        for (int nt = 0; nt < 8; nt++) {
            s[nt][0] = __expf(s[nt][0] - nm0); sum0 += s[nt][0];
            s[nt][1] = __expf(s[nt][1] - nm0); sum0 += s[nt][1];
            s[nt][2] = __expf(s[nt][2] - nm1); sum1 += s[nt][2];
            s[nt][3] = __expf(s[nt][3] - nm1); sum1 += s[nt][3];
        }
        sum0 += __shfl_xor_sync(0xffffffffu, sum0, 1);
        sum0 += __shfl_xor_sync(0xffffffffu, sum0, 2);
        sum1 += __shfl_xor_sync(0xffffffffu, sum1, 1);
        sum1 += __shfl_xor_sync(0xffffffffu, sum1, 2);
        l0 = l0 * c0 + sum0; l1 = l1 * c1 + sum1;
        m0 = nm0; m1 = nm1;
        #pragma unroll
        for (int nt = 0; nt < 8; nt++) {
            o[nt][0] *= c0; o[nt][1] *= c0;
            o[nt][2] *= c1; o[nt][3] *= c1;
        }

        // ---- stage P (split hi/lo) into smem, per-warp private rows ----
        #pragma unroll
        for (int nt = 0; nt < 8; nt++) {
            int c = nt * 8 + tq * 2;
            int r = qw + g;
            float h0, lo0, h1, lo1;
            split2(s[nt][0], h0, lo0); split2(s[nt][1], h1, lo1);
            *reinterpret_cast<float2*>(&Ph[r][c]) = make_float2(h0, h1);
            *reinterpret_cast<float2*>(&Pl[r][c]) = make_float2(lo0, lo1);
            split2(s[nt][2], h0, lo0); split2(s[nt][3], h1, lo1);
            *reinterpret_cast<float2*>(&Ph[r + 8][c]) = make_float2(h0, h1);
            *reinterpret_cast<float2*>(&Pl[r + 8][c]) = make_float2(lo0, lo1);
        }
        __syncwarp();

        // ---- O += P @ V (3xTF32) ----
        #pragma unroll
        for (int ks = 0; ks < 8; ks++) {
            int kk = ks * 8 + tq;
            int r = qw + g;
            float ah[4] = { Ph[r][kk], Ph[r + 8][kk], Ph[r][kk + 4], Ph[r + 8][kk + 4] };
            float al[4] = { Pl[r][kk], Pl[r + 8][kk], Pl[r][kk + 4], Pl[r + 8][kk + 4] };
            #pragma unroll
            for (int nt = 0; nt < 8; nt++) {
                int n = nt * 8 + g;
                float bh[2] = { Vh[n][kk], Vh[n][kk + 4] };
                float bl[2] = { Vl[n][kk], Vl[n][kk + 4] };
                mma8(o[nt], ah, bl);
                mma8(o[nt], al, bh);
                mma8(o[nt], ah, bh);
            }
        }
    }

    // ---- epilogue ----
    float inv0 = 1.0f / l0, inv1 = 1.0f / l1;
    int r0 = q0 + qw + g, r1 = r0 + 8;
    #pragma unroll
    for (int nt = 0; nt < 8; nt++) {
        int d = nt * 8 + tq * 2;
        *reinterpret_cast<float2*>(&g_ctx[((size_t)r0 * NB + b) * EE + h * HD + d]) =
            make_float2(o[nt][0] * inv0, o[nt][1] * inv0);
        *reinterpret_cast<float2*>(&g_ctx[((size_t)r1 * NB + b) * EE + h * HD + d]) =
            make_float2(o[nt][2] * inv1, o[nt][3] * inv1);
    }
}

// ---------------- router: logits = xn @ router_w, argmax ----------------
__global__ void router_kernel(const float* __restrict__ rw) {
    int t = blockIdx.x;
    const float* x = g_xn + (size_t)t * EE;
    float a[NEXP];
    #pragma unroll
    for (int e = 0; e < NEXP; e++) a[e] = 0.f;
    for (int k = threadIdx.x; k < EE; k += 256) {
        float xv = x[k];
        #pragma unroll
        for (int e = 0; e < NEXP; e++) a[e] += xv * rw[k * NEXP + e];
    }
    __shared__ float red[8][NEXP];
    #pragma unroll
    for (int e = 0; e < NEXP; e++) {
        float v = a[e];
        #pragma unroll
        for (int o = 16; o > 0; o >>= 1) v += __shfl_xor_sync(0xffffffffu, v, o);
        if ((threadIdx.x & 31) == 0) red[threadIdx.x >> 5][e] = v;
    }
    __syncthreads();
    if (threadIdx.x == 0) {
        int best = 0; float bv = -1e30f;
        #pragma unroll
        for (int e = 0; e < NEXP; e++) {
            float sum = 0.f;
            #pragma unroll
            for (int w = 0; w < 8; w++) sum += red[w][e];
            if (sum > bv) { bv = sum; best = e; }
        }
        g_eid[t] = best;
    }
}

// ---------------- capacity: sequential per-expert scan ----------------
__global__ void capacity_kernel() {
    int e = threadIdx.x;
    if (e >= NEXP) return;
    int cnt = 0;
    for (int t = 0; t < TOK; t++) {
        if (g_eid[t] == e && cnt < CAPN) {
            g_list[e * CAPN + cnt] = t;
            cnt++;
        }
    }
    g_cnt[e] = cnt;
}

// ---------------- MoE GEMM1 (1xTF32): H = gelu(gather(xn) @ wi[e]) ----------------
__global__ __launch_bounds__(256, 2) void moe1_tc_kernel(const float* __restrict__ wi) {
    int e = blockIdx.z;
    int cnt = g_cnt[e];
    int row0 = blockIdx.y * 128;
    if (row0 >= cnt) return;
    int col0 = blockIdx.x * 128;
    float acc[2][8][4];
    #pragma unroll
    for (int a = 0; a < 2; a++)
        #pragma unroll
        for (int b = 0; b < 8; b++)
            #pragma unroll
            for (int c = 0; c < 4; c++) acc[a][b][c] = 0.f;
    gemm_tc_core<1, false>(g_xn, EE, wi + (size_t)e * EE * FF, FF, EE, row0, col0,
                           g_list + e * CAPN, cnt, acc);

    int warp = threadIdx.x >> 5, lane = threadIdx.x & 31;
    int wm = (warp & 3) * 32, wn = (warp >> 2) * 64;
    int g = lane >> 2, tq = lane & 3;
    #pragma unroll
    for (int mt = 0; mt < 2; mt++) {
        #pragma unroll
        for (int p = 0; p < 2; p++) {
            int r = row0 + wm + mt * 16 + g + p * 8;
            if (r < cnt) {
                #pragma unroll
                for (int nt = 0; nt < 8; nt++) {
                    int c = col0 + wn + nt * 8 + tq * 2;
                    float x0 = acc[mt][nt][p * 2], x1 = acc[mt][nt][p * 2 + 1];
                    float g0 = 0.5f * x0 * (1.0f + erff(x0 * 0.70710678118654752f));
                    float g1 = 0.5f * x1 * (1.0f + erff(x1 * 0.70710678118654752f));
                    *reinterpret_cast<float2*>(
                        &g_h[((size_t)e * CAPN + r) * FF + c]) = make_float2(g0, g1);
                }
            }
        }
    }
}

// ---------------- init output with residual ----------------
__global__ void init_out_kernel(float* __restrict__ out) {
    int i = blockIdx.x * blockDim.x + threadIdx.x;
    out[i] = g_x[i];
}

// ---------------- MoE GEMM2 (1xTF32): out[token] += H @ wo[e] ----------------
__global__ __launch_bounds__(256, 2) void moe2_tc_kernel(const float* __restrict__ wo,
                                                         float* __restrict__ out) {
    int e = blockIdx.z;
    int cnt = g_cnt[e];
    int row0 = blockIdx.y * 128;
    if (row0 >= cnt) return;
    int col0 = blockIdx.x * 128;
    float acc[2][8][4];
    #pragma unroll
    for (int a = 0; a < 2; a++)
        #pragma unroll
        for (int b = 0; b < 8; b++)
            #pragma unroll
            for (int c = 0; c < 4; c++) acc[a][b][c] = 0.f;
    gemm_tc_core<1, false>(g_h + (size_t)e * CAPN * FF, FF, wo + (size_t)e * FF * EE, EE,
                           FF, row0, col0, nullptr, cnt, acc);

    int warp = threadIdx.x >> 5, lane = threadIdx.x & 31;
    int wm = (warp & 3) * 32, wn = (warp >> 2) * 64;
    int g = lane >> 2, tq = lane & 3;
    #pragma unroll
    for (int mt = 0; mt < 2; mt++) {
        #pragma unroll
        for (int p = 0; p < 2; p++) {
            int r = row0 + wm + mt * 16 + g + p * 8;
            if (r < cnt) {
                int tok = g_list[e * CAPN + r];
                #pragma unroll
                for (int nt = 0; nt < 8; nt++) {
                    int c = col0 + wn + nt * 8 + tq * 2;
                    size_t i0 = (size_t)tok * EE + c;
                    out[i0]     += acc[mt][nt][p * 2];
                    out[i0 + 1] += acc[mt][nt][p * 2 + 1];
                }
            }
        }
    }
}

// ---------------- launch ----------------
extern "C" void kernel_launch(void* const* d_in, const int* in_sizes, int n_in,
                              void* d_out, int out_size) {
    const float* q     = (const float*)d_in[0];
    const float* k     = (const float*)d_in[1];
    const float* v     = (const float*)d_in[2];
    const float* in_w  = (const float*)d_in[3];
    const float* in_b  = (const float*)d_in[4];
    const float* out_w = (const float*)d_in[5];
    const float* out_b = (const float*)d_in[6];
    const float* n1s   = (const float*)d_in[7];
    const float* n1b   = (const float*)d_in[8];
    const float* n2s   = (const float*)d_in[9];
    const float* n2b   = (const float*)d_in[10];
    const float* rw    = (const float*)d_in[11];
    const float* wi    = (const float*)d_in[12];
    const float* wo    = (const float*)d_in[13];
    float* out = (float*)d_out;

    static int attr_done = 0;
    if (!attr_done) {
        cudaFuncSetAttribute(attn_tc_kernel, cudaFuncAttributeMaxDynamicSharedMemorySize,
                             ATTN_SMEM_FLOATS * 4);
        attr_done = 1;
    }

    ln1_rope_kernel<<<dim3(TOK, 3), 256>>>(q, k, v, n1s, n1b);
    qkv_tc_kernel<<<dim3(EE / 128, TOK / 128, 3), 256>>>(in_w, in_b);
    attn_tc_kernel<<<dim3(SQ / 128, NB * NH), 256, ATTN_SMEM_FLOATS * 4>>>();
    outproj_tc_kernel<<<dim3(EE / 128, TOK / 128), 256>>>(out_w, out_b, q);
    ln2_kernel<<<TOK, 256>>>(n2s, n2b);
    router_kernel<<<TOK, 256>>>(rw);
    capacity_kernel<<<1, 32>>>();
    moe1_tc_kernel<<<dim3(FF / 128, CAPN / 128, NEXP), 256>>>(wi);
    init_out_kernel<<<(TOK * EE) / 256, 256>>>(out);
    moe2_tc_kernel<<<dim3(EE / 128, CAPN / 128, NEXP), 256>>>(wo, out);
}